// round 3
// baseline (speedup 1.0000x reference)
#include <cuda_runtime.h>
#include <math.h>

#define NNODES 50000
#define NEDGES 800000
#define INDIM  256
#define HID    64
#define OUTD   64

// ---------------- scratch (device globals; no runtime allocation) ----------------
__device__ float g_Wcat1[INDIM * 512];          // [256,512] = [W1l | W1r] columns
__device__ float g_Wcat2[HID * 128];            // [64,128]  = [W2l | W2r]
__device__ float g_XW1[(size_t)NNODES * 512];   // layer1 projected: [xl(256) | xr(256)]
__device__ float g_H1[(size_t)NNODES * 64];     // post layer1 (LN+ReLU)
__device__ float g_XW2[(size_t)NNODES * 128];   // layer2 projected: [xl(64) | xr(64)]
__device__ int   g_deg[NNODES];
__device__ int   g_cur[NNODES];
__device__ int   g_offs[NNODES + 1];
__device__ int   g_esrc[NEDGES];

// ---------------- weight packing ----------------
__global__ void pack1_kernel(const float* __restrict__ Wl, const float* __restrict__ Wr) {
    int i = blockIdx.x * blockDim.x + threadIdx.x;
    if (i >= INDIM * 512) return;
    int k = i >> 9, n = i & 511;
    g_Wcat1[i] = (n < 256) ? Wl[k * 256 + n] : Wr[k * 256 + (n - 256)];
}
__global__ void pack2_kernel(const float* __restrict__ Wl, const float* __restrict__ Wr) {
    int i = blockIdx.x * blockDim.x + threadIdx.x;
    if (i >= HID * 128) return;
    int k = i >> 7, n = i & 127;
    g_Wcat2[i] = (n < 64) ? Wl[k * 64 + n] : Wr[k * 64 + (n - 64)];
}

// ---------------- CSR build ----------------
__global__ void zero_kernel() {
    int i = blockIdx.x * blockDim.x + threadIdx.x;
    if (i < NNODES) { g_deg[i] = 0; g_cur[i] = 0; }
}
__global__ void count_kernel(const int* __restrict__ ei) {
    int e = blockIdx.x * blockDim.x + threadIdx.x;
    if (e >= NEDGES) return;
    atomicAdd(&g_deg[ei[NEDGES + e]], 1);
}
__global__ void scan_kernel() {
    __shared__ int sh[1024];
    __shared__ int carry;
    int t = threadIdx.x;
    if (t == 0) carry = 0;
    __syncthreads();
    for (int base = 0; base < NNODES; base += 1024) {
        int i = base + t;
        int v = (i < NNODES) ? g_deg[i] : 0;
        sh[t] = v;
        __syncthreads();
        for (int off = 1; off < 1024; off <<= 1) {
            int add = (t >= off) ? sh[t - off] : 0;
            __syncthreads();
            sh[t] += add;
            __syncthreads();
        }
        int incl = sh[t] + carry;
        if (i < NNODES) g_offs[i + 1] = incl;
        __syncthreads();
        if (t == 1023) carry = incl;
        __syncthreads();
    }
    if (t == 0) g_offs[0] = 0;
}
__global__ void scatter_kernel(const int* __restrict__ ei) {
    int e = blockIdx.x * blockDim.x + threadIdx.x;
    if (e >= NEDGES) return;
    int s = ei[e];
    int d = ei[NEDGES + e];
    int p = g_offs[d] + atomicAdd(&g_cur[d], 1);
    g_esrc[p] = s;
}

// ---------------- fp32 GEMM: C[M,Ncols] = A[M,K] @ B[K,Ncols] ----------------
// 128x128 tile, BK=8, 256 threads, 8x8 microtile.
// REQUIRES: Ncols % 128 == 0, K % 8 == 0 (true for both call sites: 512/256, 128/64).
__global__ void __launch_bounds__(256) sgemm_kernel(const float* __restrict__ A,
                                                    const float* __restrict__ B,
                                                    float* __restrict__ C,
                                                    int M, int Ncols, int K) {
    __shared__ float As[8][128];
    __shared__ float Bs[8][128];
    int tid = threadIdx.x;
    int tx = tid & 15, ty = tid >> 4;
    int bx = blockIdx.x, by = blockIdx.y;
    int rowC = by * 128 + ty * 8;
    int colC = bx * 128 + tx * 8;

    int aRow = tid >> 1, aCol = (tid & 1) * 4;
    int bRow = tid >> 5, bCol = (tid & 31) * 4;
    int arow_g = by * 128 + aRow;

    float acc[8][8];
#pragma unroll
    for (int i = 0; i < 8; i++)
#pragma unroll
        for (int j = 0; j < 8; j++) acc[i][j] = 0.f;

    for (int k0 = 0; k0 < K; k0 += 8) {
        float4 av = make_float4(0.f, 0.f, 0.f, 0.f);
        if (arow_g < M)
            av = *(const float4*)(A + (size_t)arow_g * K + k0 + aCol);
        As[aCol + 0][aRow] = av.x;
        As[aCol + 1][aRow] = av.y;
        As[aCol + 2][aRow] = av.z;
        As[aCol + 3][aRow] = av.w;
        float4 bv = *(const float4*)(B + (size_t)(k0 + bRow) * Ncols + bx * 128 + bCol);
        *(float4*)&Bs[bRow][bCol] = bv;
        __syncthreads();
#pragma unroll
        for (int kk = 0; kk < 8; kk++) {
            float a[8], b[8];
            *(float4*)(a)     = *(const float4*)&As[kk][ty * 8];
            *(float4*)(a + 4) = *(const float4*)&As[kk][ty * 8 + 4];
            *(float4*)(b)     = *(const float4*)&Bs[kk][tx * 8];
            *(float4*)(b + 4) = *(const float4*)&Bs[kk][tx * 8 + 4];
#pragma unroll
            for (int i = 0; i < 8; i++)
#pragma unroll
                for (int j = 0; j < 8; j++)
                    acc[i][j] = fmaf(a[i], b[j], acc[i][j]);
        }
        __syncthreads();
    }
#pragma unroll
    for (int i = 0; i < 8; i++) {
        int r = rowC + i;
        if (r >= M) continue;
        float* cptr = C + (size_t)r * Ncols + colC;
        float4 v0 = make_float4(acc[i][0], acc[i][1], acc[i][2], acc[i][3]);
        float4 v1 = make_float4(acc[i][4], acc[i][5], acc[i][6], acc[i][7]);
        *(float4*)(cptr) = v0;
        *(float4*)(cptr + 4) = v1;
    }
}

__device__ __forceinline__ float warp_sum(float v) {
#pragma unroll
    for (int off = 16; off > 0; off >>= 1)
        v += __shfl_xor_sync(0xffffffffu, v, off);
    return v;
}

// ---------------- Layer-1 aggregation: warp per node, 4 heads x 64 chans ----------------
// lane holds channels cbase..cbase+3 of heads hA=lane>>4 and hA+2.
__global__ void __launch_bounds__(256) agg1_kernel(const float* __restrict__ att1,
                                                   const float* __restrict__ b1,
                                                   const float* __restrict__ lg,
                                                   const float* __restrict__ lb) {
    int node = blockIdx.x * (blockDim.x >> 5) + (threadIdx.x >> 5);
    if (node >= NNODES) return;
    int lane = threadIdx.x & 31;
    int cbase = (lane * 4) & 63;
    int hA = lane >> 4;

    float attA[4], attB[4];
#pragma unroll
    for (int j = 0; j < 4; j++) {
        attA[j] = att1[hA * 64 + cbase + j];
        attB[j] = att1[(hA + 2) * 64 + cbase + j];
    }
    const float* row_i = g_XW1 + (size_t)node * 512;
    float xra[4], xrb[4];
    {
        float4 t0 = *(const float4*)(row_i + 256 + lane * 4);
        float4 t1 = *(const float4*)(row_i + 256 + 128 + lane * 4);
        xra[0] = t0.x; xra[1] = t0.y; xra[2] = t0.z; xra[3] = t0.w;
        xrb[0] = t1.x; xrb[1] = t1.y; xrb[2] = t1.z; xrb[3] = t1.w;
    }

    float m0 = -3.0e38f, m1 = -3.0e38f, d0 = 0.f, d1 = 0.f;
    float acc0[4] = {0.f, 0.f, 0.f, 0.f}, acc1[4] = {0.f, 0.f, 0.f, 0.f};

    int beg = g_offs[node];
    int nb = g_offs[node + 1] - beg;
    for (int k = -1; k < nb; k++) {
        int s = (k < 0) ? node : g_esrc[beg + k];
        const float* rs = g_XW1 + (size_t)s * 512;
        float xla[4], xlb[4];
        {
            float4 t0 = *(const float4*)(rs + lane * 4);
            float4 t1 = *(const float4*)(rs + 128 + lane * 4);
            xla[0] = t0.x; xla[1] = t0.y; xla[2] = t0.z; xla[3] = t0.w;
            xlb[0] = t1.x; xlb[1] = t1.y; xlb[2] = t1.z; xlb[3] = t1.w;
        }
        float pA = 0.f, pB = 0.f;
#pragma unroll
        for (int j = 0; j < 4; j++) {
            float gA = xla[j] + xra[j];
            gA = fmaxf(gA, 0.2f * gA);
            pA = fmaf(gA, attA[j], pA);
            float gB = xlb[j] + xrb[j];
            gB = fmaxf(gB, 0.2f * gB);
            pB = fmaf(gB, attB[j], pB);
        }
#pragma unroll
        for (int off = 1; off < 16; off <<= 1) {
            pA += __shfl_xor_sync(0xffffffffu, pA, off);
            pB += __shfl_xor_sync(0xffffffffu, pB, off);
        }
        // online softmax, head A
        if (pA > m0) {
            float sc = __expf(m0 - pA);
            d0 *= sc;
#pragma unroll
            for (int j = 0; j < 4; j++) acc0[j] *= sc;
            m0 = pA;
        }
        float w0 = __expf(pA - m0);
        d0 += w0;
#pragma unroll
        for (int j = 0; j < 4; j++) acc0[j] = fmaf(w0, xla[j], acc0[j]);
        // head B
        if (pB > m1) {
            float sc = __expf(m1 - pB);
            d1 *= sc;
#pragma unroll
            for (int j = 0; j < 4; j++) acc1[j] *= sc;
            m1 = pB;
        }
        float w1 = __expf(pB - m1);
        d1 += w1;
#pragma unroll
        for (int j = 0; j < 4; j++) acc1[j] = fmaf(w1, xlb[j], acc1[j]);
    }

    float inv0 = 1.f / (d0 + 1e-16f);
    float inv1 = 1.f / (d1 + 1e-16f);
    float o[4];
#pragma unroll
    for (int j = 0; j < 4; j++) {
        float s = acc0[j] * inv0 + acc1[j] * inv1;
        s += __shfl_xor_sync(0xffffffffu, s, 16);   // add other head pair (same channels)
        o[j] = 0.25f * s + b1[cbase + j];
    }
    // LayerNorm over 64 chans (each channel duplicated on lanes l and l^16)
    float lsum = o[0] + o[1] + o[2] + o[3];
    float mu = warp_sum(lsum) * (1.f / 128.f);
    float lsq = 0.f;
#pragma unroll
    for (int j = 0; j < 4; j++) {
        float dv = o[j] - mu;
        lsq = fmaf(dv, dv, lsq);
    }
    float var = warp_sum(lsq) * (1.f / 128.f);
    float inv = rsqrtf(var + 1e-5f);
    if (lane < 16) {
        float r[4];
#pragma unroll
        for (int j = 0; j < 4; j++) {
            float v = (o[j] - mu) * inv * lg[cbase + j] + lb[cbase + j];
            r[j] = fmaxf(v, 0.f);   // ReLU
        }
        *(float4*)(g_H1 + (size_t)node * 64 + cbase) = make_float4(r[0], r[1], r[2], r[3]);
    }
}

// ---------------- Layer-2 aggregation: warp per node, 1 head x 64 chans ----------------
__global__ void __launch_bounds__(256) agg2_kernel(const float* __restrict__ att2,
                                                   const float* __restrict__ b2,
                                                   const float* __restrict__ lg,
                                                   const float* __restrict__ lb,
                                                   float* __restrict__ out) {
    int node = blockIdx.x * (blockDim.x >> 5) + (threadIdx.x >> 5);
    if (node >= NNODES) return;
    int lane = threadIdx.x & 31;
    int c = lane * 2;

    float at[2] = {att2[c], att2[c + 1]};
    const float* row_i = g_XW2 + (size_t)node * 128;
    float2 xr = *(const float2*)(row_i + 64 + c);

    float m = -3.0e38f, den = 0.f;
    float acc[2] = {0.f, 0.f};

    int beg = g_offs[node];
    int nb = g_offs[node + 1] - beg;
    for (int k = -1; k < nb; k++) {
        int s = (k < 0) ? node : g_esrc[beg + k];
        float2 xl = *(const float2*)(g_XW2 + (size_t)s * 128 + c);
        float g0 = xl.x + xr.x; g0 = fmaxf(g0, 0.2f * g0);
        float g1 = xl.y + xr.y; g1 = fmaxf(g1, 0.2f * g1);
        float p = fmaf(g0, at[0], g1 * at[1]);
        p = warp_sum(p);
        if (p > m) {
            float sc = __expf(m - p);
            den *= sc; acc[0] *= sc; acc[1] *= sc;
            m = p;
        }
        float w = __expf(p - m);
        den += w;
        acc[0] = fmaf(w, xl.x, acc[0]);
        acc[1] = fmaf(w, xl.y, acc[1]);
    }
    float invd = 1.f / (den + 1e-16f);
    float o0 = acc[0] * invd + b2[c];
    float o1 = acc[1] * invd + b2[c + 1];
    float mu = warp_sum(o0 + o1) * (1.f / 64.f);
    float dv0 = o0 - mu, dv1 = o1 - mu;
    float var = warp_sum(dv0 * dv0 + dv1 * dv1) * (1.f / 64.f);
    float inv = rsqrtf(var + 1e-5f);
    float r0 = dv0 * inv * lg[c] + lb[c];
    float r1 = dv1 * inv * lg[c + 1] + lb[c + 1];
    *(float2*)(out + (size_t)node * 64 + c) = make_float2(r0, r1);
}

// ---------------- launch ----------------
extern "C" void kernel_launch(void* const* d_in, const int* in_sizes, int n_in,
                              void* d_out, int out_size) {
    const float* x    = (const float*)d_in[0];
    const int*   ei   = (const int*)d_in[1];
    const float* W1l  = (const float*)d_in[2];
    const float* W1r  = (const float*)d_in[3];
    const float* att1 = (const float*)d_in[4];
    const float* b1   = (const float*)d_in[5];
    const float* ln1g = (const float*)d_in[6];
    const float* ln1b = (const float*)d_in[7];
    const float* W2l  = (const float*)d_in[8];
    const float* W2r  = (const float*)d_in[9];
    const float* att2 = (const float*)d_in[10];
    const float* b2   = (const float*)d_in[11];
    const float* ln2g = (const float*)d_in[12];
    const float* ln2b = (const float*)d_in[13];
    float* out = (float*)d_out;

    void *pXW1, *pXW2, *pH1, *pW1, *pW2;
    cudaGetSymbolAddress(&pXW1, g_XW1);
    cudaGetSymbolAddress(&pXW2, g_XW2);
    cudaGetSymbolAddress(&pH1,  g_H1);
    cudaGetSymbolAddress(&pW1,  g_Wcat1);
    cudaGetSymbolAddress(&pW2,  g_Wcat2);

    pack1_kernel<<<(INDIM * 512 + 255) / 256, 256>>>(W1l, W1r);
    pack2_kernel<<<(HID * 128 + 255) / 256, 256>>>(W2l, W2r);
    zero_kernel<<<(NNODES + 255) / 256, 256>>>();
    count_kernel<<<(NEDGES + 255) / 256, 256>>>(ei);
    scan_kernel<<<1, 1024>>>();
    scatter_kernel<<<(NEDGES + 255) / 256, 256>>>(ei);

    // layer 1 projection: [N,512] = x[N,256] @ Wcat1[256,512]
    sgemm_kernel<<<dim3(4, (NNODES + 127) / 128), 256>>>(x, (const float*)pW1,
                                                         (float*)pXW1, NNODES, 512, INDIM);
    agg1_kernel<<<(NNODES + 7) / 8, 256>>>(att1, b1, ln1g, ln1b);

    // layer 2 projection: [N,128] = H1[N,64] @ Wcat2[64,128]
    sgemm_kernel<<<dim3(1, (NNODES + 127) / 128), 256>>>((const float*)pH1, (const float*)pW2,
                                                         (float*)pXW2, NNODES, 128, HID);
    agg2_kernel<<<(NNODES + 7) / 8, 256>>>(att2, b2, ln2g, ln2b, out);
}